// round 2
// baseline (speedup 1.0000x reference)
#include <cuda_runtime.h>
#include <math.h>

#define Hh    768
#define NB    32
#define NS    1024
#define NF    128
#define NP    256
#define NROWS (NB * NF)          // 4096

// output segment offsets (floats), concatenated in reference return order
#define OFF_MSR   0              // (B,F,2)  8192
#define OFF_AGG   8192           // (B,F,9)  36864
#define OFF_MSRS  45056          // (B,F,2)  8192
#define OFF_DIM   53248          // (B,F,2)  8192
#define OFF_KEY   61440          // (B,F,2)  8192
#define OFF_PAIR  69632         // (B,P,2)  16384
#define OFF_TYPE  86016          // (B,F,7)  28672

__device__ float g_field[NROWS * Hh];  // field_embedding scratch (12.6 MB)
__device__ float g_u[NROWS * 4];       // pair partial dots

// ---------------------------------------------------------------------------
// K1: scatter-mean. One block per (field f, batch b).
// Stage col row in smem -> warp-0 ballot scan from smem -> MLP-4 gather.
// ---------------------------------------------------------------------------
__global__ __launch_bounds__(192) void k1_scatter_mean(
    const float* __restrict__ emb, const int* __restrict__ col_ids)
{
    __shared__ int sCol[NS];
    __shared__ int sList[NS];
    __shared__ int sCnt;
    const int f   = blockIdx.x;
    const int b   = blockIdx.y;
    const int tid = threadIdx.x;

    // stage col row (coalesced, all threads)
    const int4* c4 = (const int4*)(col_ids + b * NS);
    for (int i = tid; i < NS / 4; i += 192) ((int4*)sCol)[i] = c4[i];
    __syncthreads();

    if (tid < 32) {
        int cnt = 0;
        const int target = f + 1;               // segment 0 dropped
        for (int base = 0; base < NS; base += 32) {
            int c = sCol[base + tid];
            unsigned m = __ballot_sync(0xffffffffu, c == target);
            if (c == target)
                sList[cnt + __popc(m & ((1u << tid) - 1u))] = base + tid;
            cnt += __popc(m);
        }
        if (tid == 0) sCnt = cnt;
    }
    __syncthreads();

    const int n = sCnt;
    const float4* base = (const float4*)(emb + (size_t)b * NS * Hh) + tid;
    float4 a0 = make_float4(0.f, 0.f, 0.f, 0.f);
    float4 a1 = make_float4(0.f, 0.f, 0.f, 0.f);
    float4 a2 = make_float4(0.f, 0.f, 0.f, 0.f);
    float4 a3 = make_float4(0.f, 0.f, 0.f, 0.f);
    int i = 0;
    for (; i + 4 <= n; i += 4) {
        int r0 = sList[i], r1 = sList[i+1], r2 = sList[i+2], r3 = sList[i+3];
        float4 v0 = base[r0 * (Hh / 4)];
        float4 v1 = base[r1 * (Hh / 4)];
        float4 v2 = base[r2 * (Hh / 4)];
        float4 v3 = base[r3 * (Hh / 4)];
        a0.x += v0.x; a0.y += v0.y; a0.z += v0.z; a0.w += v0.w;
        a1.x += v1.x; a1.y += v1.y; a1.z += v1.z; a1.w += v1.w;
        a2.x += v2.x; a2.y += v2.y; a2.z += v2.z; a2.w += v2.w;
        a3.x += v3.x; a3.y += v3.y; a3.z += v3.z; a3.w += v3.w;
    }
    for (; i < n; i++) {
        float4 v0 = base[sList[i] * (Hh / 4)];
        a0.x += v0.x; a0.y += v0.y; a0.z += v0.z; a0.w += v0.w;
    }
    const float inv = 1.0f / (float)(n > 0 ? n : 1);
    float4 r;
    r.x = (a0.x + a1.x + a2.x + a3.x) * inv;
    r.y = (a0.y + a1.y + a2.y + a3.y) * inv;
    r.z = (a0.z + a1.z + a2.z + a3.z) * inv;
    r.w = (a0.w + a1.w + a2.w + a3.w) * inv;
    ((float4*)(g_field + (size_t)(b * NF + f) * Hh))[tid] = r;
}

// ---------------------------------------------------------------------------
// K2: heads GEMM (4096 x 768) x (768 x 28) fused with log_softmax.
// Class layout: [0:2)=msr [2:11)=agg [11:13)=dim [13:15)=msrs [15:17)=key
//               [17:24)=type [24:26)=u1(pair top) [26:28)=u2(pair bottom)
// 128 threads/block: 8 row-groups(4 rows) x 4 class-groups(7 classes) x 4 k-splits.
// ---------------------------------------------------------------------------
#define TILE 32
#define NC   28
#define WS   772   // padded row stride in floats (768 + 4, 16B stride odd)

__device__ __forceinline__ void write_lsm(float* dst, const float* l, int n)
{
    float m = l[0];
    for (int i = 1; i < n; i++) m = fmaxf(m, l[i]);
    float s = 0.f;
    for (int i = 0; i < n; i++) s += expf(l[i] - m);
    const float lse = m + logf(s);
    for (int i = 0; i < n; i++) dst[i] = l[i] - lse;
}

__global__ __launch_bounds__(128) void k2_heads(
    const float* __restrict__ Wmsr,  const float* __restrict__ bmsr,
    const float* __restrict__ Wagg,  const float* __restrict__ bagg,
    const float* __restrict__ Wdim,  const float* __restrict__ bdim,
    const float* __restrict__ Wmsrs, const float* __restrict__ bmsrs,
    const float* __restrict__ Wkey,  const float* __restrict__ bkey,
    const float* __restrict__ Wpair, const float* __restrict__ Wtype,
    const float* __restrict__ btype,
    float* __restrict__ out)
{
    extern __shared__ float sh[];
    float* sWt = sh;              // [NC][WS] : W transposed, class-major
    float* sV  = sh + NC * WS;    // [TILE][WS]
    __shared__ float sLog[TILE][NC + 1];
    __shared__ float sB[NC];

    const int tid  = threadIdx.x;
    const int nt   = 128;
    const int row0 = blockIdx.x * TILE;

    // ---- stage W^T (class-major rows) ----
    for (int i = tid; i < Hh * 2; i += nt) { int h = i >> 1, c = i & 1;    sWt[(0  + c) * WS + h] = Wmsr[i]; }
    for (int i = tid; i < Hh * 9; i += nt) { int h = i / 9, c = i - h * 9; sWt[(2  + c) * WS + h] = Wagg[i]; }
    for (int i = tid; i < Hh * 2; i += nt) { int h = i >> 1, c = i & 1;    sWt[(11 + c) * WS + h] = Wdim[i]; }
    for (int i = tid; i < Hh * 2; i += nt) { int h = i >> 1, c = i & 1;    sWt[(13 + c) * WS + h] = Wmsrs[i]; }
    for (int i = tid; i < Hh * 2; i += nt) { int h = i >> 1, c = i & 1;    sWt[(15 + c) * WS + h] = Wkey[i]; }
    for (int i = tid; i < Hh * 7; i += nt) { int h = i / 7, c = i - h * 7; sWt[(17 + c) * WS + h] = Wtype[i]; }
    for (int i = tid; i < Hh * 2; i += nt) {
        int h = i >> 1, c = i & 1;
        sWt[(24 + c) * WS + h] = Wpair[i];                    // W_pair[0:H, c]
        sWt[(26 + c) * WS + h] = Wpair[(Hh + h) * 2 + c];     // W_pair[H:2H, c]
    }

    if (tid < NC) {
        float bv = 0.f;
        if      (tid < 2)  bv = bmsr[tid];
        else if (tid < 11) bv = bagg[tid - 2];
        else if (tid < 13) bv = bdim[tid - 11];
        else if (tid < 15) bv = bmsrs[tid - 13];
        else if (tid < 17) bv = bkey[tid - 15];
        else if (tid < 24) bv = btype[tid - 17];
        sB[tid] = bv;                    // pair classes: bias added in K3
    }

    // ---- stage V tile ----
    for (int i = tid; i < TILE * (Hh / 4); i += nt) {
        int r = i / (Hh / 4), c4 = i - r * (Hh / 4);
        float4 v = ((const float4*)(g_field + (size_t)(row0 + r) * Hh))[c4];
        *((float4*)(sV + r * WS + c4 * 4)) = v;
    }
    __syncthreads();

    // ---- compute: micro-tile 4 rows x 7 classes, 4-way k split ----
    const int kq = tid & 3;
    const int cg = (tid >> 2) & 3;
    const int rg = tid >> 4;       // 0..7

    float acc[4][7];
#pragma unroll
    for (int a = 0; a < 4; a++)
#pragma unroll
        for (int c = 0; c < 7; c++) acc[a][c] = 0.f;

    const float* vp = sV  + (rg * 4) * WS;
    const float* wp = sWt + (cg * 7) * WS;

#pragma unroll 2
    for (int j = kq; j < Hh / 4; j += 4) {
        const int k = j * 4;
        float4 p[4], q[7];
#pragma unroll
        for (int a = 0; a < 4; a++) p[a] = *(const float4*)(vp + a * WS + k);
#pragma unroll
        for (int c = 0; c < 7; c++) q[c] = *(const float4*)(wp + c * WS + k);
#pragma unroll
        for (int a = 0; a < 4; a++)
#pragma unroll
            for (int c = 0; c < 7; c++) {
                acc[a][c] += p[a].x * q[c].x + p[a].y * q[c].y
                           + p[a].z * q[c].z + p[a].w * q[c].w;
            }
    }

    // reduce 4-way k-split (kq = lane bits 0-1)
#pragma unroll
    for (int a = 0; a < 4; a++)
#pragma unroll
        for (int c = 0; c < 7; c++) {
            float v = acc[a][c];
            v += __shfl_xor_sync(0xffffffffu, v, 1);
            v += __shfl_xor_sync(0xffffffffu, v, 2);
            acc[a][c] = v;
        }
    if (kq == 0) {
#pragma unroll
        for (int a = 0; a < 4; a++)
#pragma unroll
            for (int c = 0; c < 7; c++)
                sLog[rg * 4 + a][cg * 7 + c] = acc[a][c];
    }
    __syncthreads();

    // ---- per-row log_softmax + writes ----
    if (tid < TILE) {
        const int row = row0 + tid;
        float l[NC];
#pragma unroll
        for (int c = 0; c < NC; c++) l[c] = sLog[tid][c] + sB[c];

        write_lsm(out + OFF_MSR  + row * 2, l + 0,  2);
        write_lsm(out + OFF_AGG  + row * 9, l + 2,  9);
        write_lsm(out + OFF_MSRS + row * 2, l + 13, 2);
        write_lsm(out + OFF_DIM  + row * 2, l + 11, 2);
        write_lsm(out + OFF_KEY  + row * 2, l + 15, 2);
        write_lsm(out + OFF_TYPE + row * 7, l + 17, 7);

        float* u = g_u + row * 4;   // pair partials (no bias)
        u[0] = l[24]; u[1] = l[25]; u[2] = l[26]; u[3] = l[27];
    }
}

// ---------------------------------------------------------------------------
// K3: pair head from precomputed partial dots. One thread per (b, p).
// ---------------------------------------------------------------------------
__global__ __launch_bounds__(256) void k3_pair(
    const int* __restrict__ pidx, const float* __restrict__ bpair,
    float* __restrict__ out)
{
    const int p = blockIdx.x * blockDim.x + threadIdx.x;   // 0 .. B*P-1
    if (p >= NB * NP) return;
    const int b  = p >> 8;                                 // p / NP
    const int i1 = pidx[2 * p];
    const int i2 = pidx[2 * p + 1];
    const float* u1 = g_u + (size_t)(b * NF + i1) * 4;
    const float* u2 = g_u + (size_t)(b * NF + i2) * 4;
    const float l0 = u1[0] + u2[2] + bpair[0];
    const float l1 = u1[1] + u2[3] + bpair[1];
    const float m  = fmaxf(l0, l1);
    const float lse = m + logf(expf(l0 - m) + expf(l1 - m));
    out[OFF_PAIR + 2 * p]     = l0 - lse;
    out[OFF_PAIR + 2 * p + 1] = l1 - lse;
}

// ---------------------------------------------------------------------------
extern "C" void kernel_launch(void* const* d_in, const int* in_sizes, int n_in,
                              void* d_out, int out_size)
{
    const float* emb  = (const float*)d_in[0];
    const int*   col  = (const int*)d_in[1];
    const int*   pidx = (const int*)d_in[2];
    const int wb = n_in - 14;
    const float* Wmsr  = (const float*)d_in[wb + 0];
    const float* bmsr  = (const float*)d_in[wb + 1];
    const float* Wagg  = (const float*)d_in[wb + 2];
    const float* bagg  = (const float*)d_in[wb + 3];
    const float* Wdim  = (const float*)d_in[wb + 4];
    const float* bdim  = (const float*)d_in[wb + 5];
    const float* Wmsrs = (const float*)d_in[wb + 6];
    const float* bmsrs = (const float*)d_in[wb + 7];
    const float* Wkey  = (const float*)d_in[wb + 8];
    const float* bkey  = (const float*)d_in[wb + 9];
    const float* Wpair = (const float*)d_in[wb + 10];
    const float* bpair = (const float*)d_in[wb + 11];
    const float* Wtype = (const float*)d_in[wb + 12];
    const float* btype = (const float*)d_in[wb + 13];
    float* out = (float*)d_out;

    k1_scatter_mean<<<dim3(NF, NB), 192>>>(emb, col);

    const int shmem = (NC + TILE) * WS * (int)sizeof(float);  // 185,280 B
    cudaFuncSetAttribute(k2_heads, cudaFuncAttributeMaxDynamicSharedMemorySize, shmem);
    k2_heads<<<NROWS / TILE, 128, shmem>>>(Wmsr, bmsr, Wagg, bagg, Wdim, bdim,
                                           Wmsrs, bmsrs, Wkey, bkey,
                                           Wpair, Wtype, btype, out);

    k3_pair<<<(NB * NP) / 256, 256>>>(pidx, bpair, out);
}

// round 6
// speedup vs baseline: 1.3635x; 1.3635x over previous
#include <cuda_runtime.h>
#include <math.h>

#define Hh    768
#define NB    32
#define NS    1024
#define NF    128
#define NP    256
#define NROWS (NB * NF)          // 4096
#define NC    28
#define NSEG  129                // col ids 0..128
#define CAP   64                 // max tokens per (b,field)
#define FG    8                  // fields per fused block

// output segment offsets (floats), reference return order
#define OFF_MSR   0              // (B,F,2)
#define OFF_AGG   8192           // (B,F,9)
#define OFF_MSRS  45056          // (B,F,2)
#define OFF_DIM   53248          // (B,F,2)
#define OFF_KEY   61440          // (B,F,2)
#define OFF_PAIR  69632          // (B,P,2)
#define OFF_TYPE  86016          // (B,F,7)

__device__ int   g_list[NB * (NSEG + 1) * CAP];
__device__ int   g_cnt[NB * NSEG];
__device__ float g_wT[NC * Hh];                  // class-major transposed weights
__device__ float g_bias[NC];                     // pair classes: 0 (bias in K3)
__device__ float g_u[NROWS * 4];                 // pair partial dots

// ---------------------------------------------------------------------------
// k0: blocks 0..31 build token lists (1 warp per batch row, deterministic
// match_any rank scan). Blocks 32..39 transpose weights into g_wT.
// ---------------------------------------------------------------------------
__global__ __launch_bounds__(256) void k0_prep(
    const int* __restrict__ col,
    const float* __restrict__ Wmsr,  const float* __restrict__ bmsr,
    const float* __restrict__ Wagg,  const float* __restrict__ bagg,
    const float* __restrict__ Wdim,  const float* __restrict__ bdim,
    const float* __restrict__ Wmsrs, const float* __restrict__ bmsrs,
    const float* __restrict__ Wkey,  const float* __restrict__ bkey,
    const float* __restrict__ Wpair, const float* __restrict__ Wtype,
    const float* __restrict__ btype)
{
    const int blk = blockIdx.x;
    if (blk < NB) {
        if (threadIdx.x >= 32) return;
        const int lane = threadIdx.x;
        __shared__ int sCur[NSEG];
        for (int i = lane; i < NSEG; i += 32) sCur[i] = 0;
        __syncwarp();

        int c_arr[32];
        const int* crow = col + blk * NS;
#pragma unroll
        for (int ch = 0; ch < 32; ch++) c_arr[ch] = crow[ch * 32 + lane];

#pragma unroll 1
        for (int ch = 0; ch < 32; ch++) {
            const int c = c_arr[ch];
            const bool act = (c != 0);
            const unsigned amask = __ballot_sync(0xffffffffu, act);
            if (act) {
                const unsigned m = __match_any_sync(amask, c);
                const int leader = __ffs(m) - 1;
                const int rank = __popc(m & ((1u << lane) - 1u));
                int base = 0;
                if (lane == leader) { base = sCur[c]; sCur[c] = base + __popc(m); }
                base = __shfl_sync(amask, base, leader);
                const int pos = base + rank;
                if (pos < CAP)
                    g_list[(blk * (NSEG + 1) + c) * CAP + pos] = ch * 32 + lane;
            }
            __syncwarp();
        }
        __syncwarp();
        for (int i = lane; i < NSEG; i += 32)
            g_cnt[blk * NSEG + i] = min(sCur[i], CAP);
    } else {
        // weight transpose
        const int t = (blk - NB) * 256 + threadIdx.x;   // 0..2047
        for (int idx = t; idx < NC * Hh; idx += 8 * 256) {
            const int c = idx / Hh, h = idx - c * Hh;
            float w;
            if      (c < 2)  w = Wmsr [h * 2 + c];
            else if (c < 11) w = Wagg [h * 9 + (c - 2)];
            else if (c < 13) w = Wdim [h * 2 + (c - 11)];
            else if (c < 15) w = Wmsrs[h * 2 + (c - 13)];
            else if (c < 17) w = Wkey [h * 2 + (c - 15)];
            else if (c < 24) w = Wtype[h * 7 + (c - 17)];
            else if (c < 26) w = Wpair[h * 2 + (c - 24)];
            else             w = Wpair[(Hh + h) * 2 + (c - 26)];
            g_wT[c * Hh + h] = w;
        }
        if (blk == NB && threadIdx.x < NC) {
            const int c = threadIdx.x;
            float bv = 0.f;
            if      (c < 2)  bv = bmsr [c];
            else if (c < 11) bv = bagg [c - 2];
            else if (c < 13) bv = bdim [c - 11];
            else if (c < 15) bv = bmsrs[c - 13];
            else if (c < 17) bv = bkey [c - 15];
            else if (c < 24) bv = btype[c - 17];
            g_bias[c] = bv;
        }
    }
}

// ---------------------------------------------------------------------------
// k1_fused: one block per (fgroup of 8 fields, batch). Gather means into
// registers, compute all 28 head logits in-block, fused log_softmax + writes.
// ---------------------------------------------------------------------------
__device__ __forceinline__ void write_lsm(float* dst, const float* l, int n)
{
    float m = l[0];
    for (int i = 1; i < n; i++) m = fmaxf(m, l[i]);
    float s = 0.f;
    for (int i = 0; i < n; i++) s += expf(l[i] - m);
    const float lse = m + logf(s);
    for (int i = 0; i < n; i++) dst[i] = l[i] - lse;
}

__global__ __launch_bounds__(192) void k1_fused(
    const float* __restrict__ emb, float* __restrict__ out)
{
    const int fg   = blockIdx.x;              // 0..15
    const int b    = blockIdx.y;              // 0..31
    const int tid  = threadIdx.x;             // 0..191 (h-slice owner)
    const int lane = tid & 31;
    const int w    = tid >> 5;                // warp 0..5

    __shared__ float sRed[6][NC][FG];
    __shared__ float sLog[FG][NC];

    const float4* ebase = (const float4*)(emb + (size_t)b * NS * Hh) + tid;

    float4 v[FG];
#pragma unroll 1
    for (int f = 0; f < FG; f++) {
        const int tgt = fg * FG + f + 1;      // col target (segment 0 dropped)
        const int n = g_cnt[b * NSEG + tgt];
        const int* lst = g_list + (b * (NSEG + 1) + tgt) * CAP;
        float4 a0 = make_float4(0.f, 0.f, 0.f, 0.f);
        float4 a1 = make_float4(0.f, 0.f, 0.f, 0.f);
        float4 a2 = make_float4(0.f, 0.f, 0.f, 0.f);
        float4 a3 = make_float4(0.f, 0.f, 0.f, 0.f);
        int i = 0;
        for (; i + 4 <= n; i += 4) {
            const int r0 = lst[i], r1 = lst[i+1], r2 = lst[i+2], r3 = lst[i+3];
            float4 x0 = ebase[r0 * (Hh/4)];
            float4 x1 = ebase[r1 * (Hh/4)];
            float4 x2 = ebase[r2 * (Hh/4)];
            float4 x3 = ebase[r3 * (Hh/4)];
            a0.x += x0.x; a0.y += x0.y; a0.z += x0.z; a0.w += x0.w;
            a1.x += x1.x; a1.y += x1.y; a1.z += x1.z; a1.w += x1.w;
            a2.x += x2.x; a2.y += x2.y; a2.z += x2.z; a2.w += x2.w;
            a3.x += x3.x; a3.y += x3.y; a3.z += x3.z; a3.w += x3.w;
        }
        for (; i < n; i++) {
            float4 x0 = ebase[lst[i] * (Hh/4)];
            a0.x += x0.x; a0.y += x0.y; a0.z += x0.z; a0.w += x0.w;
        }
        const float inv = 1.0f / (float)(n > 0 ? n : 1);
        v[f].x = (a0.x + a1.x + a2.x + a3.x) * inv;
        v[f].y = (a0.y + a1.y + a2.y + a3.y) * inv;
        v[f].z = (a0.z + a1.z + a2.z + a3.z) * inv;
        v[f].w = (a0.w + a1.w + a2.w + a3.w) * inv;
    }

    // ---- head logits: 28 classes, 8 fields, reduce over 192 h-threads ----
    const float4* wt = (const float4*)g_wT;   // [NC][192]
#pragma unroll 1
    for (int c = 0; c < NC; c++) {
        const float4 q = wt[c * (Hh/4) + tid];
        float s[FG];
#pragma unroll
        for (int f = 0; f < FG; f++)
            s[f] = v[f].x * q.x + v[f].y * q.y + v[f].z * q.z + v[f].w * q.w;
#pragma unroll
        for (int f = 0; f < FG; f++) {
            s[f] += __shfl_xor_sync(0xffffffffu, s[f], 16);
            s[f] += __shfl_xor_sync(0xffffffffu, s[f], 8);
            s[f] += __shfl_xor_sync(0xffffffffu, s[f], 4);
            s[f] += __shfl_xor_sync(0xffffffffu, s[f], 2);
            s[f] += __shfl_xor_sync(0xffffffffu, s[f], 1);
        }
        if (lane == 0) {
#pragma unroll
            for (int f = 0; f < FG; f++) sRed[w][c][f] = s[f];
        }
    }
    __syncthreads();

    // NC*FG = 224 > 192 threads — strided reduction loop covers all cells
    for (int idx = tid; idx < NC * FG; idx += 192) {
        const int c = idx >> 3, f = idx & 7;
        float s = sRed[0][c][f] + sRed[1][c][f] + sRed[2][c][f]
                + sRed[3][c][f] + sRed[4][c][f] + sRed[5][c][f] + g_bias[c];
        sLog[f][c] = s;
    }
    __syncthreads();

    if (tid < FG) {
        const int field = fg * FG + tid;
        const int row = b * NF + field;
        float l[NC];
#pragma unroll
        for (int c = 0; c < NC; c++) l[c] = sLog[tid][c];

        write_lsm(out + OFF_MSR  + row * 2, l + 0,  2);
        write_lsm(out + OFF_AGG  + row * 9, l + 2,  9);
        write_lsm(out + OFF_MSRS + row * 2, l + 13, 2);
        write_lsm(out + OFF_DIM  + row * 2, l + 11, 2);
        write_lsm(out + OFF_KEY  + row * 2, l + 15, 2);
        write_lsm(out + OFF_TYPE + row * 7, l + 17, 7);

        float* u = g_u + row * 4;          // pair partials, no bias
        u[0] = l[24]; u[1] = l[25]; u[2] = l[26]; u[3] = l[27];
    }
}

// ---------------------------------------------------------------------------
// K3: pair head from precomputed partial dots.
// ---------------------------------------------------------------------------
__global__ __launch_bounds__(256) void k3_pair(
    const int* __restrict__ pidx, const float* __restrict__ bpair,
    float* __restrict__ out)
{
    const int p = blockIdx.x * blockDim.x + threadIdx.x;   // 0 .. B*P-1
    if (p >= NB * NP) return;
    const int b  = p >> 8;
    const int i1 = pidx[2 * p];
    const int i2 = pidx[2 * p + 1];
    const float* u1 = g_u + (size_t)(b * NF + i1) * 4;
    const float* u2 = g_u + (size_t)(b * NF + i2) * 4;
    const float l0 = u1[0] + u2[2] + bpair[0];
    const float l1 = u1[1] + u2[3] + bpair[1];
    const float m  = fmaxf(l0, l1);
    const float lse = m + logf(expf(l0 - m) + expf(l1 - m));
    out[OFF_PAIR + 2 * p]     = l0 - lse;
    out[OFF_PAIR + 2 * p + 1] = l1 - lse;
}

// ---------------------------------------------------------------------------
extern "C" void kernel_launch(void* const* d_in, const int* in_sizes, int n_in,
                              void* d_out, int out_size)
{
    const float* emb  = (const float*)d_in[0];
    const int*   col  = (const int*)d_in[1];
    const int*   pidx = (const int*)d_in[2];
    const int wb = n_in - 14;
    const float* Wmsr  = (const float*)d_in[wb + 0];
    const float* bmsr  = (const float*)d_in[wb + 1];
    const float* Wagg  = (const float*)d_in[wb + 2];
    const float* bagg  = (const float*)d_in[wb + 3];
    const float* Wdim  = (const float*)d_in[wb + 4];
    const float* bdim  = (const float*)d_in[wb + 5];
    const float* Wmsrs = (const float*)d_in[wb + 6];
    const float* bmsrs = (const float*)d_in[wb + 7];
    const float* Wkey  = (const float*)d_in[wb + 8];
    const float* bkey  = (const float*)d_in[wb + 9];
    const float* Wpair = (const float*)d_in[wb + 10];
    const float* bpair = (const float*)d_in[wb + 11];
    const float* Wtype = (const float*)d_in[wb + 12];
    const float* btype = (const float*)d_in[wb + 13];
    float* out = (float*)d_out;

    k0_prep<<<NB + 8, 256>>>(col, Wmsr, bmsr, Wagg, bagg, Wdim, bdim,
                             Wmsrs, bmsrs, Wkey, bkey, Wpair, Wtype, btype);

    k1_fused<<<dim3(NF / FG, NB), 192>>>(emb, out);

    k3_pair<<<(NB * NP) / 256, 256>>>(pidx, bpair, out);
}